// round 2
// baseline (speedup 1.0000x reference)
#include <cuda_runtime.h>
#include <cuda_bf16.h>
#include <cstdint>
#include <cstddef>

// ---------------------------------------------------------------------------
// Problem constants
// ---------------------------------------------------------------------------
#define BATCH     2
#define SEQ       2048
#define TOKENS    (BATCH * SEQ)          // 4096
#define D_MODEL   2048
#define D_INNER   4096
#define D_XB      1024
#define HEADDIM   64
#define D_STATE   64
#define NHEADS    64
#define NKV       16
#define INTER     8192
#define D_IN_PROJ (D_INNER + D_XB + D_XB + D_INNER + NHEADS)  // 10304
#define EPSV      1e-5f

// zxbcdt row layout offsets
#define OFF_Z   0
#define OFF_X   4096
#define OFF_B   5120
#define OFF_C   6144
#define OFF_DT  10240

// ---------------------------------------------------------------------------
// Scratch (static device allocation; no cudaMalloc allowed)
// MLP1 is aliased over ZX: ZX is dead after gate_norm (step 4), MLP1 is first
// written at step 6. ZX (42.2M floats) > MLP1 (33.6M floats), so it fits.
// ---------------------------------------------------------------------------
#define H_ELEMS    ((size_t)TOKENS * D_MODEL)          //  8388608
#define ZX_ELEMS   ((size_t)TOKENS * D_IN_PROJ)        // 42205184
#define Y_ELEMS    ((size_t)TOKENS * D_INNER)          // 16777216
#define TMP_ELEMS  ((size_t)TOKENS * D_MODEL)          //  8388608

#define H_OFF    ((size_t)0)
#define ZX_OFF   (H_OFF + H_ELEMS)
#define Y_OFF    (ZX_OFF + ZX_ELEMS)
#define TMP_OFF  (Y_OFF + Y_ELEMS)
#define TOTAL_SCRATCH (TMP_OFF + TMP_ELEMS)            // ~75.8M floats (~303 MB)

#define MLP1_OFF ZX_OFF                                 // alias

__device__ float g_scratch[TOTAL_SCRATCH];

// ---------------------------------------------------------------------------
// Helpers
// ---------------------------------------------------------------------------
__device__ __forceinline__ float gelu_tanh(float x) {
    float x3 = x * x * x;
    float t = tanhf(0.7978845608028654f * (x + 0.044715f * x3));
    return 0.5f * x * (1.0f + t);
}

__device__ __forceinline__ float silu_f(float x) {
    return x / (1.0f + expf(-x));
}

// ---------------------------------------------------------------------------
// LayerNorm: one row (2048) per CTA, 256 threads (8 floats each)
// ---------------------------------------------------------------------------
__global__ void __launch_bounds__(256) ln_kernel(
    const float* __restrict__ X, const float* __restrict__ w,
    const float* __restrict__ b, float* __restrict__ H)
{
    int row = blockIdx.x;
    int tid = threadIdx.x;
    const float4* x4 = (const float4*)(X + (size_t)row * D_MODEL);

    float4 va = x4[tid];
    float4 vb = x4[tid + 256];
    float sum = va.x + va.y + va.z + va.w + vb.x + vb.y + vb.z + vb.w;
    float sq  = va.x*va.x + va.y*va.y + va.z*va.z + va.w*va.w
              + vb.x*vb.x + vb.y*vb.y + vb.z*vb.z + vb.w*vb.w;

    #pragma unroll
    for (int off = 16; off > 0; off >>= 1) {
        sum += __shfl_xor_sync(0xffffffffu, sum, off);
        sq  += __shfl_xor_sync(0xffffffffu, sq,  off);
    }
    __shared__ float s1[8], s2[8];
    int wid = tid >> 5, lane = tid & 31;
    if (lane == 0) { s1[wid] = sum; s2[wid] = sq; }
    __syncthreads();
    float tot = 0.f, totq = 0.f;
    #pragma unroll
    for (int i = 0; i < 8; i++) { tot += s1[i]; totq += s2[i]; }
    float mean = tot * (1.0f / D_MODEL);
    float var  = totq * (1.0f / D_MODEL) - mean * mean;
    float rstd = rsqrtf(var + EPSV);

    float4* h4 = (float4*)(H + (size_t)row * D_MODEL);
    const float4* w4 = (const float4*)w;
    const float4* b4 = (const float4*)b;
    float4 wa = w4[tid], ba = b4[tid];
    float4 wb = w4[tid + 256], bb = b4[tid + 256];
    float4 oa, ob;
    oa.x = (va.x - mean) * rstd * wa.x + ba.x;
    oa.y = (va.y - mean) * rstd * wa.y + ba.y;
    oa.z = (va.z - mean) * rstd * wa.z + ba.z;
    oa.w = (va.w - mean) * rstd * wa.w + ba.w;
    ob.x = (vb.x - mean) * rstd * wb.x + bb.x;
    ob.y = (vb.y - mean) * rstd * wb.y + bb.y;
    ob.z = (vb.z - mean) * rstd * wb.z + bb.z;
    ob.w = (vb.w - mean) * rstd * wb.w + bb.w;
    h4[tid]       = oa;
    h4[tid + 256] = ob;
}

// ---------------------------------------------------------------------------
// SGEMM (NT): C[M,N] = A[M,K] (row-major) * B[N,K]^T (row-major weights)
// BM=128, BN=64, BK=16, 128 threads, 8x8 microtile.
// EPI: 0 = plain, 1 = +bias then gelu, 2 = +bias +add1 +add2
// ---------------------------------------------------------------------------
#define BM 128
#define BN 64
#define BKt 16
#define AS_STRIDE (BM + 4)
#define BS_STRIDE (BN + 4)

template <int EPI>
__global__ void __launch_bounds__(128) sgemm_nt(
    const float* __restrict__ A, const float* __restrict__ B,
    float* __restrict__ C, int M, int N, int K,
    const float* __restrict__ bias,
    const float* __restrict__ add1,
    const float* __restrict__ add2)
{
    __shared__ float As[BKt][AS_STRIDE];
    __shared__ float Bs[BKt][BS_STRIDE];

    int tid = threadIdx.x;
    int m0 = blockIdx.y * BM;
    int n0 = blockIdx.x * BN;
    int tx = tid & 7;     // n-dir, 8 threads * 8 = 64
    int ty = tid >> 3;    // m-dir, 16 threads * 8 = 128

    float acc[8][8];
    #pragma unroll
    for (int i = 0; i < 8; i++)
        #pragma unroll
        for (int j = 0; j < 8; j++) acc[i][j] = 0.f;

    for (int k0 = 0; k0 < K; k0 += BKt) {
        // Load A tile: 128x16 = 512 float4, 4 per thread
        #pragma unroll
        for (int i = 0; i < 4; i++) {
            int idx = tid + 128 * i;
            int m   = idx >> 2;
            int kq  = (idx & 3) * 4;
            float4 v = *(const float4*)(A + (size_t)(m0 + m) * K + k0 + kq);
            As[kq + 0][m] = v.x;
            As[kq + 1][m] = v.y;
            As[kq + 2][m] = v.z;
            As[kq + 3][m] = v.w;
        }
        // Load B tile: 64x16 = 256 float4, 2 per thread
        #pragma unroll
        for (int i = 0; i < 2; i++) {
            int idx = tid + 128 * i;
            int n   = idx >> 2;
            int kq  = (idx & 3) * 4;
            float4 v = *(const float4*)(B + (size_t)(n0 + n) * K + k0 + kq);
            Bs[kq + 0][n] = v.x;
            Bs[kq + 1][n] = v.y;
            Bs[kq + 2][n] = v.z;
            Bs[kq + 3][n] = v.w;
        }
        __syncthreads();

        #pragma unroll
        for (int kk = 0; kk < BKt; kk++) {
            float af[8], bf[8];
            *(float4*)(af)     = *(const float4*)&As[kk][ty * 8];
            *(float4*)(af + 4) = *(const float4*)&As[kk][ty * 8 + 4];
            *(float4*)(bf)     = *(const float4*)&Bs[kk][tx * 8];
            *(float4*)(bf + 4) = *(const float4*)&Bs[kk][tx * 8 + 4];
            #pragma unroll
            for (int i = 0; i < 8; i++)
                #pragma unroll
                for (int j = 0; j < 8; j++)
                    acc[i][j] = fmaf(af[i], bf[j], acc[i][j]);
        }
        __syncthreads();
    }

    // epilogue
    float bias8[8];
    if (EPI >= 1) {
        *(float4*)(bias8)     = *(const float4*)(bias + n0 + tx * 8);
        *(float4*)(bias8 + 4) = *(const float4*)(bias + n0 + tx * 8 + 4);
    }

    #pragma unroll
    for (int i = 0; i < 8; i++) {
        size_t m = (size_t)(m0 + ty * 8 + i);
        size_t off = m * (size_t)N + n0 + tx * 8;
        float r[8];
        #pragma unroll
        for (int j = 0; j < 8; j++) r[j] = acc[i][j];
        if (EPI == 1) {
            #pragma unroll
            for (int j = 0; j < 8; j++) r[j] = gelu_tanh(r[j] + bias8[j]);
        } else if (EPI == 2) {
            float u[8], v[8];
            *(float4*)(u)     = *(const float4*)(add1 + off);
            *(float4*)(u + 4) = *(const float4*)(add1 + off + 4);
            *(float4*)(v)     = *(const float4*)(add2 + off);
            *(float4*)(v + 4) = *(const float4*)(add2 + off + 4);
            #pragma unroll
            for (int j = 0; j < 8; j++) r[j] += bias8[j] + u[j] + v[j];
        }
        *(float4*)(C + off)     = *(float4*)(r);
        *(float4*)(C + off + 4) = *(float4*)(r + 4);
    }
}

// ---------------------------------------------------------------------------
// SSD scan: 128 CTAs (batch*head), 256 threads. Thread (p = tid>>2, g = tid&3)
// owns state[p][g*16 .. g*16+15]. Double-buffered smem, one sync per step.
// ---------------------------------------------------------------------------
__global__ void __launch_bounds__(256) scan_kernel(
    const float* __restrict__ zx,
    const float* __restrict__ dt_bias,
    const float* __restrict__ A_log,
    const float* __restrict__ Dp,
    float* __restrict__ Y)
{
    int bi = blockIdx.x;
    int bb = bi >> 6;          // batch
    int h  = bi & 63;          // head
    int hk = h >> 2;           // kv head
    int tid = threadIdx.x;
    int p = tid >> 2;
    int g = tid & 3;

    __shared__ float sx[2][64], sB[2][64], sC[2][64], sdt[2];

    float Ah  = -expf(A_log[h]);
    float dtb = dt_bias[h];
    float Dh  = Dp[h];

    float s[16];
    #pragma unroll
    for (int j = 0; j < 16; j++) s[j] = 0.f;

    const size_t row_stride = (size_t)D_IN_PROJ;
    const float* base = zx + (size_t)bb * SEQ * row_stride;

    // preload l = 0 into buffer 0
    {
        const float* row = base;
        if (tid < 64)        sx[0][tid]        = row[OFF_X + hk * 64 + tid];
        else if (tid < 128)  sB[0][tid - 64]   = row[OFF_B + hk * 64 + (tid - 64)];
        else if (tid < 192)  sC[0][tid - 128]  = row[OFF_C + h * 64 + (tid - 128)];
        else if (tid == 192) sdt[0]            = row[OFF_DT + h];
    }

    for (int l = 0; l < SEQ; l++) {
        int buf = l & 1;
        __syncthreads();
        if (l + 1 < SEQ) {
            const float* row = base + (size_t)(l + 1) * row_stride;
            int nb = buf ^ 1;
            if (tid < 64)        sx[nb][tid]        = row[OFF_X + hk * 64 + tid];
            else if (tid < 128)  sB[nb][tid - 64]   = row[OFF_B + hk * 64 + (tid - 64)];
            else if (tid < 192)  sC[nb][tid - 128]  = row[OFF_C + h * 64 + (tid - 128)];
            else if (tid == 192) sdt[nb]            = row[OFF_DT + h];
        }

        float dtr = sdt[buf] + dtb;
        float dt  = (dtr > 20.f) ? dtr : log1pf(expf(dtr));
        float dA  = expf(dt * Ah);
        float xp  = sx[buf][p];
        float coeff = dt * xp;

        float yp = 0.f;
        const float* Bp = &sB[buf][g * 16];
        const float* Cp = &sC[buf][g * 16];
        #pragma unroll
        for (int j = 0; j < 16; j++) {
            s[j] = fmaf(s[j], dA, coeff * Bp[j]);
            yp   = fmaf(s[j], Cp[j], yp);
        }
        // reduce across the 4 n-groups (consecutive lanes)
        yp += __shfl_xor_sync(0xffffffffu, yp, 1);
        yp += __shfl_xor_sync(0xffffffffu, yp, 2);

        if (g == 0) {
            size_t out = ((size_t)bb * SEQ + l) * D_INNER + h * 64 + p;
            Y[out] = yp + Dh * xp;
        }
    }
}

// ---------------------------------------------------------------------------
// Gated RMSNorm: yf = y * silu(z); yf *= rsqrt(mean(yf^2)+eps) * norm_w
// one row (4096) per CTA, 256 threads, 16 elems each
// ---------------------------------------------------------------------------
__global__ void __launch_bounds__(256) gate_norm_kernel(
    float* __restrict__ Y, const float* __restrict__ ZX,
    const float* __restrict__ norm_w)
{
    int row = blockIdx.x;
    int tid = threadIdx.x;
    float4* y4 = (float4*)(Y + (size_t)row * D_INNER);
    const float4* z4 = (const float4*)(ZX + (size_t)row * D_IN_PROJ + OFF_Z);
    const float4* w4 = (const float4*)norm_w;

    float4 gv[4];
    float sq = 0.f;
    #pragma unroll
    for (int i = 0; i < 4; i++) {
        int e = tid + 256 * i;
        float4 yv = y4[e];
        float4 zv = z4[e];
        float4 gg;
        gg.x = yv.x * silu_f(zv.x);
        gg.y = yv.y * silu_f(zv.y);
        gg.z = yv.z * silu_f(zv.z);
        gg.w = yv.w * silu_f(zv.w);
        sq += gg.x*gg.x + gg.y*gg.y + gg.z*gg.z + gg.w*gg.w;
        gv[i] = gg;
    }

    #pragma unroll
    for (int off = 16; off > 0; off >>= 1)
        sq += __shfl_xor_sync(0xffffffffu, sq, off);
    __shared__ float sred[8];
    int wid = tid >> 5, lane = tid & 31;
    if (lane == 0) sred[wid] = sq;
    __syncthreads();
    float tot = 0.f;
    #pragma unroll
    for (int i = 0; i < 8; i++) tot += sred[i];
    float scale = rsqrtf(tot * (1.0f / D_INNER) + EPSV);

    #pragma unroll
    for (int i = 0; i < 4; i++) {
        int e = tid + 256 * i;
        float4 wv = w4[e];
        float4 gg = gv[i];
        gg.x *= scale * wv.x;
        gg.y *= scale * wv.y;
        gg.z *= scale * wv.z;
        gg.w *= scale * wv.w;
        y4[e] = gg;
    }
}

// ---------------------------------------------------------------------------
// Launch
// ---------------------------------------------------------------------------
extern "C" void kernel_launch(void* const* d_in, const int* in_sizes, int n_in,
                              void* d_out, int out_size)
{
    const float* hidden    = (const float*)d_in[0];
    const float* ln_w      = (const float*)d_in[1];
    const float* ln_b      = (const float*)d_in[2];
    const float* in_proj_w = (const float*)d_in[3];
    const float* dt_bias   = (const float*)d_in[4];
    const float* A_log     = (const float*)d_in[5];
    const float* Dp        = (const float*)d_in[6];
    const float* norm_w    = (const float*)d_in[7];
    const float* out_proj_w= (const float*)d_in[8];
    const float* fc1_w     = (const float*)d_in[9];
    const float* fc1_b     = (const float*)d_in[10];
    const float* fc2_w     = (const float*)d_in[11];
    const float* fc2_b     = (const float*)d_in[12];
    float* out = (float*)d_out;

    float* scratch = nullptr;
    cudaGetSymbolAddress((void**)&scratch, g_scratch);
    float* H    = scratch + H_OFF;
    float* ZX   = scratch + ZX_OFF;
    float* Y    = scratch + Y_OFF;
    float* TMP  = scratch + TMP_OFF;
    float* MLP1 = scratch + MLP1_OFF;   // aliases ZX (dead by then)

    // 1. LayerNorm
    ln_kernel<<<TOKENS, 256>>>(hidden, ln_w, ln_b, H);

    // 2. in_proj: ZX = H @ in_proj_w^T     (4096 x 10304 x 2048)
    sgemm_nt<0><<<dim3(D_IN_PROJ / BN, TOKENS / BM), 128>>>(
        H, in_proj_w, ZX, TOKENS, D_IN_PROJ, D_MODEL, nullptr, nullptr, nullptr);

    // 3. SSD scan -> Y (pre-gate)
    scan_kernel<<<BATCH * NHEADS, 256>>>(ZX, dt_bias, A_log, Dp, Y);

    // 4. gate + RMSNorm (in place on Y)
    gate_norm_kernel<<<TOKENS, 256>>>(Y, ZX, norm_w);

    // 5. out_proj: TMP = Y @ out_proj_w^T  (4096 x 2048 x 4096)
    sgemm_nt<0><<<dim3(D_MODEL / BN, TOKENS / BM), 128>>>(
        Y, out_proj_w, TMP, TOKENS, D_MODEL, D_INNER, nullptr, nullptr, nullptr);

    // 6. fc1 + gelu: MLP1 = gelu(H @ fc1_w^T + fc1_b)   (4096 x 8192 x 2048)
    sgemm_nt<1><<<dim3(INTER / BN, TOKENS / BM), 128>>>(
        H, fc1_w, MLP1, TOKENS, INTER, D_MODEL, fc1_b, nullptr, nullptr);

    // 7. fc2 + bias + mamba_out + residual -> out  (4096 x 2048 x 8192)
    sgemm_nt<2><<<dim3(D_MODEL / BN, TOKENS / BM), 128>>>(
        MLP1, fc2_w, out, TOKENS, D_MODEL, INTER, fc2_b, TMP, hidden);
}

// round 4
// speedup vs baseline: 2.2036x; 2.2036x over previous
#include <cuda_runtime.h>
#include <cuda_bf16.h>
#include <cstdint>
#include <cstddef>

// ---------------------------------------------------------------------------
// Problem constants
// ---------------------------------------------------------------------------
#define BATCH     2
#define SEQ       2048
#define TOKENS    (BATCH * SEQ)          // 4096
#define D_MODEL   2048
#define D_INNER   4096
#define D_XB      1024
#define HEADDIM   64
#define D_STATE   64
#define NHEADS    64
#define NKV       16
#define INTER     8192
#define D_IN_PROJ (D_INNER + D_XB + D_XB + D_INNER + NHEADS)  // 10304
#define EPSV      1e-5f

// zxbcdt row layout offsets
#define OFF_Z   0
#define OFF_X   4096
#define OFF_B   5120
#define OFF_C   6144
#define OFF_DT  10240

// ---------------------------------------------------------------------------
// Scratch (static; MLP1 aliases ZX which is dead after gate_norm)
// ---------------------------------------------------------------------------
#define H_ELEMS    ((size_t)TOKENS * D_MODEL)
#define ZX_ELEMS   ((size_t)TOKENS * D_IN_PROJ)
#define Y_ELEMS    ((size_t)TOKENS * D_INNER)
#define TMP_ELEMS  ((size_t)TOKENS * D_MODEL)

#define H_OFF    ((size_t)0)
#define ZX_OFF   (H_OFF + H_ELEMS)
#define Y_OFF    (ZX_OFF + ZX_ELEMS)
#define TMP_OFF  (Y_OFF + Y_ELEMS)
#define TOTAL_SCRATCH (TMP_OFF + TMP_ELEMS)
#define MLP1_OFF ZX_OFF

__device__ float g_scratch[TOTAL_SCRATCH];

// ---------------------------------------------------------------------------
// Helpers
// ---------------------------------------------------------------------------
__device__ __forceinline__ float gelu_tanh(float x) {
    float x3 = x * x * x;
    float t = tanhf(0.7978845608028654f * (x + 0.044715f * x3));
    return 0.5f * x * (1.0f + t);
}
__device__ __forceinline__ float silu_f(float x) {
    return x / (1.0f + expf(-x));
}
__device__ __forceinline__ uint32_t f2tf(float x) {
    uint32_t r;
    asm("cvt.rna.tf32.f32 %0, %1;" : "=r"(r) : "f"(x));
    return r;
}
__device__ __forceinline__ void mma_tf32(float* c, const uint32_t* a, const uint32_t* b) {
    asm volatile(
        "mma.sync.aligned.m16n8k8.row.col.f32.tf32.tf32.f32 "
        "{%0,%1,%2,%3}, {%4,%5,%6,%7}, {%8,%9}, {%0,%1,%2,%3};"
        : "+f"(c[0]), "+f"(c[1]), "+f"(c[2]), "+f"(c[3])
        : "r"(a[0]), "r"(a[1]), "r"(a[2]), "r"(a[3]), "r"(b[0]), "r"(b[1]));
}

// ---------------------------------------------------------------------------
// LayerNorm
// ---------------------------------------------------------------------------
__global__ void __launch_bounds__(256) ln_kernel(
    const float* __restrict__ X, const float* __restrict__ w,
    const float* __restrict__ b, float* __restrict__ H)
{
    int row = blockIdx.x;
    int tid = threadIdx.x;
    const float4* x4 = (const float4*)(X + (size_t)row * D_MODEL);

    float4 va = x4[tid];
    float4 vb = x4[tid + 256];
    float sum = va.x + va.y + va.z + va.w + vb.x + vb.y + vb.z + vb.w;
    float sq  = va.x*va.x + va.y*va.y + va.z*va.z + va.w*va.w
              + vb.x*vb.x + vb.y*vb.y + vb.z*vb.z + vb.w*vb.w;

    #pragma unroll
    for (int off = 16; off > 0; off >>= 1) {
        sum += __shfl_xor_sync(0xffffffffu, sum, off);
        sq  += __shfl_xor_sync(0xffffffffu, sq,  off);
    }
    __shared__ float s1[8], s2[8];
    int wid = tid >> 5, lane = tid & 31;
    if (lane == 0) { s1[wid] = sum; s2[wid] = sq; }
    __syncthreads();
    float tot = 0.f, totq = 0.f;
    #pragma unroll
    for (int i = 0; i < 8; i++) { tot += s1[i]; totq += s2[i]; }
    float mean = tot * (1.0f / D_MODEL);
    float var  = totq * (1.0f / D_MODEL) - mean * mean;
    float rstd = rsqrtf(var + EPSV);

    float4* h4 = (float4*)(H + (size_t)row * D_MODEL);
    const float4* w4 = (const float4*)w;
    const float4* b4 = (const float4*)b;
    float4 wa = w4[tid], ba = b4[tid];
    float4 wb = w4[tid + 256], bb = b4[tid + 256];
    float4 oa, ob;
    oa.x = (va.x - mean) * rstd * wa.x + ba.x;
    oa.y = (va.y - mean) * rstd * wa.y + ba.y;
    oa.z = (va.z - mean) * rstd * wa.z + ba.z;
    oa.w = (va.w - mean) * rstd * wa.w + ba.w;
    ob.x = (vb.x - mean) * rstd * wb.x + bb.x;
    ob.y = (vb.y - mean) * rstd * wb.y + bb.y;
    ob.z = (vb.z - mean) * rstd * wb.z + bb.z;
    ob.w = (vb.w - mean) * rstd * wb.w + bb.w;
    h4[tid]       = oa;
    h4[tid + 256] = ob;
}

// ---------------------------------------------------------------------------
// TF32 tensor-core GEMM (NT): C[M,N] = A[M,K] * B[N,K]^T
// BM=BN=128, BK=16, 256 threads (8 warps as 4x2), warp tile 32x64.
// m16n8k8 tf32 mma; smem [row][k] stride 20 -> conflict-free fragment LDS.
// EPI: 0 plain, 1 +bias->gelu, 2 +bias+add1+add2. N-tail predicated.
// ---------------------------------------------------------------------------
#define BKT  16
#define TSTR 20

template <int EPI>
__global__ void __launch_bounds__(256) tgemm_nt(
    const float* __restrict__ A, const float* __restrict__ B,
    float* __restrict__ C, int M, int N, int K,
    const float* __restrict__ bias,
    const float* __restrict__ add1,
    const float* __restrict__ add2)
{
    __shared__ float As[2][128 * TSTR];
    __shared__ float Bs[2][128 * TSTR];

    int tid  = threadIdx.x;
    int warp = tid >> 5, lane = tid & 31;
    int wm = warp >> 1;          // 0..3 : 32 rows each
    int wn = warp & 1;           // 0..1 : 64 cols each
    int m0 = blockIdx.y * 128;
    int n0 = blockIdx.x * 128;

    float acc[2][8][4];
    #pragma unroll
    for (int i = 0; i < 2; i++)
        #pragma unroll
        for (int j = 0; j < 8; j++)
            #pragma unroll
            for (int v = 0; v < 4; v++) acc[i][j][v] = 0.f;

    // staging: thread covers rows lm and lm+64, k-quad lk
    int lm = tid >> 2;               // 0..63
    int lk = (tid & 3) * 4;          // 0,4,8,12
    const float* Ap0 = A + (size_t)(m0 + lm)      * K + lk;
    const float* Ap1 = A + (size_t)(m0 + lm + 64) * K + lk;
    int bn0 = n0 + lm;      if (bn0 > N - 1) bn0 = N - 1;
    int bn1 = n0 + lm + 64; if (bn1 > N - 1) bn1 = N - 1;
    const float* Bp0 = B + (size_t)bn0 * K + lk;
    const float* Bp1 = B + (size_t)bn1 * K + lk;

    int s_lo = lm * TSTR + lk;
    int s_hi = (lm + 64) * TSTR + lk;

    int r = lane >> 2;   // frag row (A) / n (B)
    int q = lane & 3;    // frag k

    int nk = K / BKT;

    // prologue: stage tile 0
    {
        float4 a0 = *(const float4*)Ap0;
        float4 a1 = *(const float4*)Ap1;
        float4 b0 = *(const float4*)Bp0;
        float4 b1 = *(const float4*)Bp1;
        float4 t;
        t.x = __uint_as_float(f2tf(a0.x)); t.y = __uint_as_float(f2tf(a0.y));
        t.z = __uint_as_float(f2tf(a0.z)); t.w = __uint_as_float(f2tf(a0.w));
        *(float4*)&As[0][s_lo] = t;
        t.x = __uint_as_float(f2tf(a1.x)); t.y = __uint_as_float(f2tf(a1.y));
        t.z = __uint_as_float(f2tf(a1.z)); t.w = __uint_as_float(f2tf(a1.w));
        *(float4*)&As[0][s_hi] = t;
        t.x = __uint_as_float(f2tf(b0.x)); t.y = __uint_as_float(f2tf(b0.y));
        t.z = __uint_as_float(f2tf(b0.z)); t.w = __uint_as_float(f2tf(b0.w));
        *(float4*)&Bs[0][s_lo] = t;
        t.x = __uint_as_float(f2tf(b1.x)); t.y = __uint_as_float(f2tf(b1.y));
        t.z = __uint_as_float(f2tf(b1.z)); t.w = __uint_as_float(f2tf(b1.w));
        *(float4*)&Bs[0][s_hi] = t;
    }
    __syncthreads();

    for (int kt = 0; kt < nk; kt++) {
        int buf = kt & 1;
        float4 na0, na1, nb0, nb1;
        bool has = (kt + 1 < nk);
        if (has) {
            size_t off = (size_t)(kt + 1) * BKT;
            na0 = *(const float4*)(Ap0 + off);
            na1 = *(const float4*)(Ap1 + off);
            nb0 = *(const float4*)(Bp0 + off);
            nb1 = *(const float4*)(Bp1 + off);
        }

        // compute on buf
        const float* Ab = As[buf];
        const float* Bb = Bs[buf];
        #pragma unroll
        for (int ks = 0; ks < 2; ks++) {
            int kb = ks * 8;
            uint32_t af[2][4];
            #pragma unroll
            for (int ti = 0; ti < 2; ti++) {
                const float* ap = Ab + (wm * 32 + ti * 16 + r) * TSTR + kb + q;
                af[ti][0] = __float_as_uint(ap[0]);
                af[ti][1] = __float_as_uint(ap[8 * TSTR]);
                af[ti][2] = __float_as_uint(ap[4]);
                af[ti][3] = __float_as_uint(ap[8 * TSTR + 4]);
            }
            uint32_t bf[8][2];
            #pragma unroll
            for (int tj = 0; tj < 8; tj++) {
                const float* bp = Bb + (wn * 64 + tj * 8 + r) * TSTR + kb + q;
                bf[tj][0] = __float_as_uint(bp[0]);
                bf[tj][1] = __float_as_uint(bp[4]);
            }
            #pragma unroll
            for (int ti = 0; ti < 2; ti++)
                #pragma unroll
                for (int tj = 0; tj < 8; tj++)
                    mma_tf32(acc[ti][tj], af[ti], bf[tj]);
        }

        if (has) {
            int nb = buf ^ 1;
            float4 t;
            t.x = __uint_as_float(f2tf(na0.x)); t.y = __uint_as_float(f2tf(na0.y));
            t.z = __uint_as_float(f2tf(na0.z)); t.w = __uint_as_float(f2tf(na0.w));
            *(float4*)&As[nb][s_lo] = t;
            t.x = __uint_as_float(f2tf(na1.x)); t.y = __uint_as_float(f2tf(na1.y));
            t.z = __uint_as_float(f2tf(na1.z)); t.w = __uint_as_float(f2tf(na1.w));
            *(float4*)&As[nb][s_hi] = t;
            t.x = __uint_as_float(f2tf(nb0.x)); t.y = __uint_as_float(f2tf(nb0.y));
            t.z = __uint_as_float(f2tf(nb0.z)); t.w = __uint_as_float(f2tf(nb0.w));
            *(float4*)&Bs[nb][s_lo] = t;
            t.x = __uint_as_float(f2tf(nb1.x)); t.y = __uint_as_float(f2tf(nb1.y));
            t.z = __uint_as_float(f2tf(nb1.z)); t.w = __uint_as_float(f2tf(nb1.w));
            *(float4*)&Bs[nb][s_hi] = t;
        }
        __syncthreads();
    }

    // epilogue: hoisted per-thread bias (cols depend only on wn, tj, q)
    float bcol[8][2];
    if (EPI >= 1) {
        #pragma unroll
        for (int tj = 0; tj < 8; tj++) {
            int c = n0 + wn * 64 + tj * 8 + q * 2;
            if (c < N) {
                bcol[tj][0] = bias[c];
                bcol[tj][1] = bias[c + 1];
            } else {
                bcol[tj][0] = 0.f; bcol[tj][1] = 0.f;
            }
        }
    }

    #pragma unroll
    for (int ti = 0; ti < 2; ti++) {
        int r0 = m0 + wm * 32 + ti * 16 + r;
        #pragma unroll
        for (int tj = 0; tj < 8; tj++) {
            int c = n0 + wn * 64 + tj * 8 + q * 2;
            if (c >= N) continue;
            float v0 = acc[ti][tj][0], v1 = acc[ti][tj][1];
            float v2 = acc[ti][tj][2], v3 = acc[ti][tj][3];
            size_t o0 = (size_t)r0 * N + c;
            size_t o1 = (size_t)(r0 + 8) * N + c;
            if (EPI == 1) {
                v0 = gelu_tanh(v0 + bcol[tj][0]); v1 = gelu_tanh(v1 + bcol[tj][1]);
                v2 = gelu_tanh(v2 + bcol[tj][0]); v3 = gelu_tanh(v3 + bcol[tj][1]);
            } else if (EPI == 2) {
                float2 u0 = *(const float2*)(add1 + o0);
                float2 u1 = *(const float2*)(add1 + o1);
                float2 w0 = *(const float2*)(add2 + o0);
                float2 w1 = *(const float2*)(add2 + o1);
                v0 += bcol[tj][0] + u0.x + w0.x; v1 += bcol[tj][1] + u0.y + w0.y;
                v2 += bcol[tj][0] + u1.x + w1.x; v3 += bcol[tj][1] + u1.y + w1.y;
            }
            *(float2*)(C + o0) = make_float2(v0, v1);
            *(float2*)(C + o1) = make_float2(v2, v3);
        }
    }
}

// ---------------------------------------------------------------------------
// SSD scan: 128 CTAs (batch*head), 256 threads, double-buffered smem
// ---------------------------------------------------------------------------
__global__ void __launch_bounds__(256) scan_kernel(
    const float* __restrict__ zx,
    const float* __restrict__ dt_bias,
    const float* __restrict__ A_log,
    const float* __restrict__ Dp,
    float* __restrict__ Y)
{
    int bi = blockIdx.x;
    int bb = bi >> 6;
    int h  = bi & 63;
    int hk = h >> 2;
    int tid = threadIdx.x;
    int p = tid >> 2;
    int g = tid & 3;

    __shared__ float sx[2][64], sB[2][64], sC[2][64], sdt[2];

    float Ah  = -expf(A_log[h]);
    float dtb = dt_bias[h];
    float Dh  = Dp[h];

    float s[16];
    #pragma unroll
    for (int j = 0; j < 16; j++) s[j] = 0.f;

    const size_t row_stride = (size_t)D_IN_PROJ;
    const float* base = zx + (size_t)bb * SEQ * row_stride;

    {
        const float* row = base;
        if (tid < 64)        sx[0][tid]        = row[OFF_X + hk * 64 + tid];
        else if (tid < 128)  sB[0][tid - 64]   = row[OFF_B + hk * 64 + (tid - 64)];
        else if (tid < 192)  sC[0][tid - 128]  = row[OFF_C + h * 64 + (tid - 128)];
        else if (tid == 192) sdt[0]            = row[OFF_DT + h];
    }

    for (int l = 0; l < SEQ; l++) {
        int buf = l & 1;
        __syncthreads();
        if (l + 1 < SEQ) {
            const float* row = base + (size_t)(l + 1) * row_stride;
            int nb = buf ^ 1;
            if (tid < 64)        sx[nb][tid]        = row[OFF_X + hk * 64 + tid];
            else if (tid < 128)  sB[nb][tid - 64]   = row[OFF_B + hk * 64 + (tid - 64)];
            else if (tid < 192)  sC[nb][tid - 128]  = row[OFF_C + h * 64 + (tid - 128)];
            else if (tid == 192) sdt[nb]            = row[OFF_DT + h];
        }

        float dtr = sdt[buf] + dtb;
        float dt  = (dtr > 20.f) ? dtr : log1pf(expf(dtr));
        float dA  = expf(dt * Ah);
        float xp  = sx[buf][p];
        float coeff = dt * xp;

        float yp = 0.f;
        const float* Bp = &sB[buf][g * 16];
        const float* Cp = &sC[buf][g * 16];
        #pragma unroll
        for (int j = 0; j < 16; j++) {
            s[j] = fmaf(s[j], dA, coeff * Bp[j]);
            yp   = fmaf(s[j], Cp[j], yp);
        }
        yp += __shfl_xor_sync(0xffffffffu, yp, 1);
        yp += __shfl_xor_sync(0xffffffffu, yp, 2);

        if (g == 0) {
            size_t out = ((size_t)bb * SEQ + l) * D_INNER + h * 64 + p;
            Y[out] = yp + Dh * xp;
        }
    }
}

// ---------------------------------------------------------------------------
// Gated RMSNorm
// ---------------------------------------------------------------------------
__global__ void __launch_bounds__(256) gate_norm_kernel(
    float* __restrict__ Y, const float* __restrict__ ZX,
    const float* __restrict__ norm_w)
{
    int row = blockIdx.x;
    int tid = threadIdx.x;
    float4* y4 = (float4*)(Y + (size_t)row * D_INNER);
    const float4* z4 = (const float4*)(ZX + (size_t)row * D_IN_PROJ + OFF_Z);
    const float4* w4 = (const float4*)norm_w;

    float4 gv[4];
    float sq = 0.f;
    #pragma unroll
    for (int i = 0; i < 4; i++) {
        int e = tid + 256 * i;
        float4 yv = y4[e];
        float4 zv = z4[e];
        float4 gg;
        gg.x = yv.x * silu_f(zv.x);
        gg.y = yv.y * silu_f(zv.y);
        gg.z = yv.z * silu_f(zv.z);
        gg.w = yv.w * silu_f(zv.w);
        sq += gg.x*gg.x + gg.y*gg.y + gg.z*gg.z + gg.w*gg.w;
        gv[i] = gg;
    }

    #pragma unroll
    for (int off = 16; off > 0; off >>= 1)
        sq += __shfl_xor_sync(0xffffffffu, sq, off);
    __shared__ float sred[8];
    int wid = tid >> 5, lane = tid & 31;
    if (lane == 0) sred[wid] = sq;
    __syncthreads();
    float tot = 0.f;
    #pragma unroll
    for (int i = 0; i < 8; i++) tot += sred[i];
    float scale = rsqrtf(tot * (1.0f / D_INNER) + EPSV);

    #pragma unroll
    for (int i = 0; i < 4; i++) {
        int e = tid + 256 * i;
        float4 wv = w4[e];
        float4 gg = gv[i];
        gg.x *= scale * wv.x;
        gg.y *= scale * wv.y;
        gg.z *= scale * wv.z;
        gg.w *= scale * wv.w;
        y4[e] = gg;
    }
}

// ---------------------------------------------------------------------------
// Launch
// ---------------------------------------------------------------------------
extern "C" void kernel_launch(void* const* d_in, const int* in_sizes, int n_in,
                              void* d_out, int out_size)
{
    const float* hidden    = (const float*)d_in[0];
    const float* ln_w      = (const float*)d_in[1];
    const float* ln_b      = (const float*)d_in[2];
    const float* in_proj_w = (const float*)d_in[3];
    const float* dt_bias   = (const float*)d_in[4];
    const float* A_log     = (const float*)d_in[5];
    const float* Dp        = (const float*)d_in[6];
    const float* norm_w    = (const float*)d_in[7];
    const float* out_proj_w= (const float*)d_in[8];
    const float* fc1_w     = (const float*)d_in[9];
    const float* fc1_b     = (const float*)d_in[10];
    const float* fc2_w     = (const float*)d_in[11];
    const float* fc2_b     = (const float*)d_in[12];
    float* out = (float*)d_out;

    float* scratch = nullptr;
    cudaGetSymbolAddress((void**)&scratch, g_scratch);
    float* H    = scratch + H_OFF;
    float* ZX   = scratch + ZX_OFF;
    float* Y    = scratch + Y_OFF;
    float* TMP  = scratch + TMP_OFF;
    float* MLP1 = scratch + MLP1_OFF;   // aliases ZX (dead by then)

    // 1. LayerNorm
    ln_kernel<<<TOKENS, 256>>>(hidden, ln_w, ln_b, H);

    // 2. in_proj: ZX = H @ in_proj_w^T  (4096 x 10304 x 2048), N-tail predicated
    tgemm_nt<0><<<dim3((D_IN_PROJ + 127) / 128, TOKENS / 128), 256>>>(
        H, in_proj_w, ZX, TOKENS, D_IN_PROJ, D_MODEL, nullptr, nullptr, nullptr);

    // 3. SSD scan -> Y (pre-gate)
    scan_kernel<<<BATCH * NHEADS, 256>>>(ZX, dt_bias, A_log, Dp, Y);

    // 4. gate + RMSNorm (in place on Y)
    gate_norm_kernel<<<TOKENS, 256>>>(Y, ZX, norm_w);

    // 5. out_proj: TMP = Y @ out_proj_w^T  (4096 x 2048 x 4096)
    tgemm_nt<0><<<dim3(D_MODEL / 128, TOKENS / 128), 256>>>(
        Y, out_proj_w, TMP, TOKENS, D_MODEL, D_INNER, nullptr, nullptr, nullptr);

    // 6. fc1 + gelu: MLP1 = gelu(H @ fc1_w^T + fc1_b)  (4096 x 8192 x 2048)
    tgemm_nt<1><<<dim3(INTER / 128, TOKENS / 128), 256>>>(
        H, fc1_w, MLP1, TOKENS, INTER, D_MODEL, fc1_b, nullptr, nullptr);

    // 7. fc2 + bias + mamba_out + residual -> out  (4096 x 2048 x 8192)
    tgemm_nt<2><<<dim3(D_MODEL / 128, TOKENS / 128), 256>>>(
        MLP1, fc2_w, out, TOKENS, D_MODEL, INTER, fc2_b, TMP, hidden);
}

// round 6
// speedup vs baseline: 3.5458x; 1.6091x over previous
#include <cuda_runtime.h>
#include <cuda_fp16.h>
#include <cstdint>
#include <cstddef>

// ---------------------------------------------------------------------------
// Problem constants
// ---------------------------------------------------------------------------
#define BATCH     2
#define SEQ       2048
#define TOKENS    (BATCH * SEQ)          // 4096
#define D_MODEL   2048
#define D_INNER   4096
#define D_XB      1024
#define HEADDIM   64
#define D_STATE   64
#define NHEADS    64
#define NKV       16
#define INTER     8192
#define D_IN_PROJ (D_INNER + D_XB + D_XB + D_INNER + NHEADS)  // 10304
#define EPSV      1e-5f

// zxbcdt row layout offsets
#define OFF_Z   0
#define OFF_X   4096
#define OFF_B   5120
#define OFF_C   6144
#define OFF_DT  10240

// ---------------------------------------------------------------------------
// Scratch. fp32 region + fp16 region. MLP1(fp16) aliases ZX (dead after
// gate_norm; fc1 writes MLP1 afterwards).
// ---------------------------------------------------------------------------
#define ZX_ELEMS   ((size_t)TOKENS * D_IN_PROJ)
#define YF_ELEMS   ((size_t)TOKENS * D_INNER)
#define TMP_ELEMS  ((size_t)TOKENS * D_MODEL)

#define WIP_H  ((size_t)D_IN_PROJ * D_MODEL)
#define WOP_H  ((size_t)D_MODEL * D_INNER)
#define W1_H   ((size_t)INTER * D_MODEL)
#define W2_H   ((size_t)D_MODEL * INTER)
#define H16_H  ((size_t)TOKENS * D_MODEL)
#define Y16_H  ((size_t)TOKENS * D_INNER)

#define ZX_OFF   ((size_t)0)
#define YF_OFF   (ZX_OFF + ZX_ELEMS)
#define TMP_OFF  (YF_OFF + YF_ELEMS)
#define F16_OFF  (TMP_OFF + TMP_ELEMS)
#define F16_FLOATS ((WIP_H + WOP_H + W1_H + W2_H + H16_H + Y16_H + 16) / 2)
#define TOTAL_SCRATCH (F16_OFF + F16_FLOATS)

__device__ float g_scratch[TOTAL_SCRATCH];

#define WIP_OFF  ((size_t)0)
#define WOP_OFF  (WIP_OFF + WIP_H)
#define W1_OFF   (WOP_OFF + WOP_H)
#define W2_OFF   (W1_OFF + W1_H)
#define H16_OFF  (W2_OFF + W2_H)
#define Y16_OFF  (H16_OFF + H16_H)

// ---------------------------------------------------------------------------
// Helpers
// ---------------------------------------------------------------------------
__device__ __forceinline__ float gelu_tanh(float x) {
    float x3 = x * x * x;
    float t = tanhf(0.7978845608028654f * (x + 0.044715f * x3));
    return 0.5f * x * (1.0f + t);
}
__device__ __forceinline__ float silu_f(float x) {
    return x / (1.0f + expf(-x));
}
__device__ __forceinline__ uint32_t smem_u32(const void* p) {
    uint32_t a;
    asm("{ .reg .u64 t; cvta.to.shared.u64 t, %1; cvt.u32.u64 %0, t; }" : "=r"(a) : "l"(p));
    return a;
}
__device__ __forceinline__ void mma_f16(float* c, const uint32_t* a, const uint32_t* b) {
    asm volatile(
        "mma.sync.aligned.m16n8k16.row.col.f32.f16.f16.f32 "
        "{%0,%1,%2,%3}, {%4,%5,%6,%7}, {%8,%9}, {%0,%1,%2,%3};"
        : "+f"(c[0]), "+f"(c[1]), "+f"(c[2]), "+f"(c[3])
        : "r"(a[0]), "r"(a[1]), "r"(a[2]), "r"(a[3]), "r"(b[0]), "r"(b[1]));
}

// ---------------------------------------------------------------------------
// fp32 -> fp16 bulk convert (n multiple of 8)
// ---------------------------------------------------------------------------
__global__ void __launch_bounds__(256) cvt_f16_kernel(
    const float* __restrict__ src, __half* __restrict__ dst, size_t n)
{
    size_t i = ((size_t)blockIdx.x * 256 + threadIdx.x) * 8;
    if (i >= n) return;
    float4 a = *(const float4*)(src + i);
    float4 b = *(const float4*)(src + i + 4);
    __half2 h0 = __floats2half2_rn(a.x, a.y);
    __half2 h1 = __floats2half2_rn(a.z, a.w);
    __half2 h2 = __floats2half2_rn(b.x, b.y);
    __half2 h3 = __floats2half2_rn(b.z, b.w);
    uint4 u;
    u.x = *(uint32_t*)&h0; u.y = *(uint32_t*)&h1;
    u.z = *(uint32_t*)&h2; u.w = *(uint32_t*)&h3;
    *(uint4*)(dst + i) = u;
}

// ---------------------------------------------------------------------------
// LayerNorm -> fp16 H
// ---------------------------------------------------------------------------
__global__ void __launch_bounds__(256) ln_kernel(
    const float* __restrict__ X, const float* __restrict__ w,
    const float* __restrict__ b, __half* __restrict__ H16)
{
    int row = blockIdx.x;
    int tid = threadIdx.x;
    const float4* x4 = (const float4*)(X + (size_t)row * D_MODEL);

    float4 va = x4[tid];
    float4 vb = x4[tid + 256];
    float sum = va.x + va.y + va.z + va.w + vb.x + vb.y + vb.z + vb.w;
    float sq  = va.x*va.x + va.y*va.y + va.z*va.z + va.w*va.w
              + vb.x*vb.x + vb.y*vb.y + vb.z*vb.z + vb.w*vb.w;

    #pragma unroll
    for (int off = 16; off > 0; off >>= 1) {
        sum += __shfl_xor_sync(0xffffffffu, sum, off);
        sq  += __shfl_xor_sync(0xffffffffu, sq,  off);
    }
    __shared__ float s1[8], s2[8];
    int wid = tid >> 5, lane = tid & 31;
    if (lane == 0) { s1[wid] = sum; s2[wid] = sq; }
    __syncthreads();
    float tot = 0.f, totq = 0.f;
    #pragma unroll
    for (int i = 0; i < 8; i++) { tot += s1[i]; totq += s2[i]; }
    float mean = tot * (1.0f / D_MODEL);
    float var  = totq * (1.0f / D_MODEL) - mean * mean;
    float rstd = rsqrtf(var + EPSV);

    const float4* w4 = (const float4*)w;
    const float4* b4 = (const float4*)b;
    float4 wa = w4[tid], ba = b4[tid];
    float4 wb = w4[tid + 256], bb = b4[tid + 256];
    float4 oa, ob;
    oa.x = (va.x - mean) * rstd * wa.x + ba.x;
    oa.y = (va.y - mean) * rstd * wa.y + ba.y;
    oa.z = (va.z - mean) * rstd * wa.z + ba.z;
    oa.w = (va.w - mean) * rstd * wa.w + ba.w;
    ob.x = (vb.x - mean) * rstd * wb.x + bb.x;
    ob.y = (vb.y - mean) * rstd * wb.y + bb.y;
    ob.z = (vb.z - mean) * rstd * wb.z + bb.z;
    ob.w = (vb.w - mean) * rstd * wb.w + bb.w;

    __half2* h2 = (__half2*)(H16 + (size_t)row * D_MODEL);
    h2[tid * 2]             = __floats2half2_rn(oa.x, oa.y);
    h2[tid * 2 + 1]         = __floats2half2_rn(oa.z, oa.w);
    h2[(tid + 256) * 2]     = __floats2half2_rn(ob.x, ob.y);
    h2[(tid + 256) * 2 + 1] = __floats2half2_rn(ob.z, ob.w);
}

// ---------------------------------------------------------------------------
// FP16 tensor-core GEMM (NT): C[M,N] = A[M,K] * B[N,K]^T, fp32 accumulate.
// BM=BN=128, BK=32 halves, 256 threads (8 warps as 4x2), warp tile 32x64.
// m16n8k16 mma; smem u32[row][20] (16 data + 4 pad) -> conflict-free LDS.
// 2-stage cp.async pipeline.
// EPI: 0 f32 out; 1 gelu(bias+x)->half out; 2 +bias+add1+add2 f32 out.
// ---------------------------------------------------------------------------
#define HSTR 20   // u32 per smem row

template <int EPI>
__global__ void __launch_bounds__(256) hgemm_nt(
    const __half* __restrict__ A, const __half* __restrict__ B,
    void* __restrict__ Cv, int N, int K,
    const float* __restrict__ bias,
    const float* __restrict__ add1,
    const float* __restrict__ add2)
{
    __shared__ uint32_t As[2][128 * HSTR];
    __shared__ uint32_t Bs[2][128 * HSTR];

    int tid  = threadIdx.x;
    int warp = tid >> 5, lane = tid & 31;
    int wm = warp >> 1;          // 0..3 : 32 rows
    int wn = warp & 1;           // 0..1 : 64 cols
    int m0 = blockIdx.y * 128;
    int n0 = blockIdx.x * 128;

    float acc[2][8][4];
    #pragma unroll
    for (int i = 0; i < 2; i++)
        #pragma unroll
        for (int j = 0; j < 8; j++)
            #pragma unroll
            for (int v = 0; v < 4; v++) acc[i][j][v] = 0.f;

    int r = lane >> 2;   // frag row / n
    int q = lane & 3;    // frag k-pair

    const int NC = K >> 5;   // BK=32 chunks

    // staging: 512 16B-chunks per tile, 2 per thread per tile
    // idx = tid + 256*i : row = idx>>2 (0..127), ck = idx&3 (k-quad of 8 halves)
    uint32_t aBase = smem_u32(&As[0][0]);
    uint32_t bBase = smem_u32(&Bs[0][0]);

    int srow0 = tid >> 2;            // 0..63
    int sck0  = tid & 3;
    int srow1 = (tid + 256) >> 2;    // 64..127
    int sck1  = sck0;

    const __half* Ag0 = A + (size_t)(m0 + srow0) * K + sck0 * 8;
    const __half* Ag1 = A + (size_t)(m0 + srow1) * K + sck1 * 8;
    int bn0 = n0 + srow0; if (bn0 > N - 1) bn0 = N - 1;
    int bn1 = n0 + srow1; if (bn1 > N - 1) bn1 = N - 1;
    const __half* Bg0 = B + (size_t)bn0 * K + sck0 * 8;
    const __half* Bg1 = B + (size_t)bn1 * K + sck1 * 8;

    uint32_t aOff0 = (srow0 * HSTR + sck0 * 4) * 4;
    uint32_t aOff1 = (srow1 * HSTR + sck1 * 4) * 4;

    auto stage = [&](int cc) {
        int bf = cc & 1;
        uint32_t aDst = aBase + bf * (128 * HSTR * 4);
        uint32_t bDst = bBase + bf * (128 * HSTR * 4);
        size_t gk = (size_t)cc * 32;
        asm volatile("cp.async.cg.shared.global [%0], [%1], 16;" :: "r"(aDst + aOff0), "l"(Ag0 + gk) : "memory");
        asm volatile("cp.async.cg.shared.global [%0], [%1], 16;" :: "r"(aDst + aOff1), "l"(Ag1 + gk) : "memory");
        asm volatile("cp.async.cg.shared.global [%0], [%1], 16;" :: "r"(bDst + aOff0), "l"(Bg0 + gk) : "memory");
        asm volatile("cp.async.cg.shared.global [%0], [%1], 16;" :: "r"(bDst + aOff1), "l"(Bg1 + gk) : "memory");
        asm volatile("cp.async.commit_group;" ::: "memory");
    };

    stage(0);

    for (int c = 0; c < NC; c++) {
        if (c + 1 < NC) stage(c + 1);
        asm volatile("cp.async.wait_group 1;" ::: "memory");
        __syncthreads();

        const uint32_t* Ab = As[c & 1];
        const uint32_t* Bb = Bs[c & 1];
        #pragma unroll
        for (int ks = 0; ks < 2; ks++) {
            int kb = ks * 8;
            uint32_t af[2][4];
            #pragma unroll
            for (int ti = 0; ti < 2; ti++) {
                const uint32_t* ap = Ab + (wm * 32 + ti * 16 + r) * HSTR + kb + q;
                af[ti][0] = ap[0];
                af[ti][1] = ap[8 * HSTR];
                af[ti][2] = ap[4];
                af[ti][3] = ap[8 * HSTR + 4];
            }
            uint32_t bfr[8][2];
            #pragma unroll
            for (int tj = 0; tj < 8; tj++) {
                const uint32_t* bp = Bb + (wn * 64 + tj * 8 + r) * HSTR + kb + q;
                bfr[tj][0] = bp[0];
                bfr[tj][1] = bp[4];
            }
            #pragma unroll
            for (int ti = 0; ti < 2; ti++)
                #pragma unroll
                for (int tj = 0; tj < 8; tj++)
                    mma_f16(acc[ti][tj], af[ti], bfr[tj]);
        }
        __syncthreads();
    }

    // epilogue (same C layout as m16n8k8): rows r0/r0+8, cols q*2, q*2+1
    float bcol[8][2];
    if (EPI >= 1) {
        #pragma unroll
        for (int tj = 0; tj < 8; tj++) {
            int c = n0 + wn * 64 + tj * 8 + q * 2;
            if (c < N) { bcol[tj][0] = bias[c]; bcol[tj][1] = bias[c + 1]; }
            else       { bcol[tj][0] = 0.f;     bcol[tj][1] = 0.f; }
        }
    }

    #pragma unroll
    for (int ti = 0; ti < 2; ti++) {
        int r0 = m0 + wm * 32 + ti * 16 + r;
        #pragma unroll
        for (int tj = 0; tj < 8; tj++) {
            int c = n0 + wn * 64 + tj * 8 + q * 2;
            if (c >= N) continue;
            float v0 = acc[ti][tj][0], v1 = acc[ti][tj][1];
            float v2 = acc[ti][tj][2], v3 = acc[ti][tj][3];
            size_t o0 = (size_t)r0 * N + c;
            size_t o1 = (size_t)(r0 + 8) * N + c;
            if (EPI == 0) {
                *(float2*)((float*)Cv + o0) = make_float2(v0, v1);
                *(float2*)((float*)Cv + o1) = make_float2(v2, v3);
            } else if (EPI == 1) {
                v0 = gelu_tanh(v0 + bcol[tj][0]); v1 = gelu_tanh(v1 + bcol[tj][1]);
                v2 = gelu_tanh(v2 + bcol[tj][0]); v3 = gelu_tanh(v3 + bcol[tj][1]);
                __half2 h0 = __floats2half2_rn(v0, v1);
                __half2 h1 = __floats2half2_rn(v2, v3);
                *(__half2*)((__half*)Cv + o0) = h0;
                *(__half2*)((__half*)Cv + o1) = h1;
            } else {
                float2 u0 = *(const float2*)(add1 + o0);
                float2 u1 = *(const float2*)(add1 + o1);
                float2 w0 = *(const float2*)(add2 + o0);
                float2 w1 = *(const float2*)(add2 + o1);
                v0 += bcol[tj][0] + u0.x + w0.x; v1 += bcol[tj][1] + u0.y + w0.y;
                v2 += bcol[tj][0] + u1.x + w1.x; v3 += bcol[tj][1] + u1.y + w1.y;
                *(float2*)((float*)Cv + o0) = make_float2(v0, v1);
                *(float2*)((float*)Cv + o1) = make_float2(v2, v3);
            }
        }
    }
}

// ---------------------------------------------------------------------------
// SSD scan: 128 CTAs, 256 threads, double-buffered smem
// ---------------------------------------------------------------------------
__global__ void __launch_bounds__(256) scan_kernel(
    const float* __restrict__ zx,
    const float* __restrict__ dt_bias,
    const float* __restrict__ A_log,
    const float* __restrict__ Dp,
    float* __restrict__ Y)
{
    int bi = blockIdx.x;
    int bb = bi >> 6;
    int h  = bi & 63;
    int hk = h >> 2;
    int tid = threadIdx.x;
    int p = tid >> 2;
    int g = tid & 3;

    __shared__ float sx[2][64], sB[2][64], sC[2][64], sdt[2];

    float Ah  = -expf(A_log[h]);
    float dtb = dt_bias[h];
    float Dh  = Dp[h];

    float s[16];
    #pragma unroll
    for (int j = 0; j < 16; j++) s[j] = 0.f;

    const size_t row_stride = (size_t)D_IN_PROJ;
    const float* base = zx + (size_t)bb * SEQ * row_stride;

    {
        const float* row = base;
        if (tid < 64)        sx[0][tid]        = row[OFF_X + hk * 64 + tid];
        else if (tid < 128)  sB[0][tid - 64]   = row[OFF_B + hk * 64 + (tid - 64)];
        else if (tid < 192)  sC[0][tid - 128]  = row[OFF_C + h * 64 + (tid - 128)];
        else if (tid == 192) sdt[0]            = row[OFF_DT + h];
    }

    for (int l = 0; l < SEQ; l++) {
        int buf = l & 1;
        __syncthreads();
        if (l + 1 < SEQ) {
            const float* row = base + (size_t)(l + 1) * row_stride;
            int nb = buf ^ 1;
            if (tid < 64)        sx[nb][tid]        = row[OFF_X + hk * 64 + tid];
            else if (tid < 128)  sB[nb][tid - 64]   = row[OFF_B + hk * 64 + (tid - 64)];
            else if (tid < 192)  sC[nb][tid - 128]  = row[OFF_C + h * 64 + (tid - 128)];
            else if (tid == 192) sdt[nb]            = row[OFF_DT + h];
        }

        float dtr = sdt[buf] + dtb;
        float dt  = (dtr > 20.f) ? dtr : log1pf(expf(dtr));
        float dA  = expf(dt * Ah);
        float xp  = sx[buf][p];
        float coeff = dt * xp;

        float yp = 0.f;
        const float* Bp = &sB[buf][g * 16];
        const float* Cp = &sC[buf][g * 16];
        #pragma unroll
        for (int j = 0; j < 16; j++) {
            s[j] = fmaf(s[j], dA, coeff * Bp[j]);
            yp   = fmaf(s[j], Cp[j], yp);
        }
        yp += __shfl_xor_sync(0xffffffffu, yp, 1);
        yp += __shfl_xor_sync(0xffffffffu, yp, 2);

        if (g == 0) {
            size_t out = ((size_t)bb * SEQ + l) * D_INNER + h * 64 + p;
            Y[out] = yp + Dh * xp;
        }
    }
}

// ---------------------------------------------------------------------------
// Gated RMSNorm -> fp16 Y
// ---------------------------------------------------------------------------
__global__ void __launch_bounds__(256) gate_norm_kernel(
    const float* __restrict__ Y, const float* __restrict__ ZX,
    const float* __restrict__ norm_w, __half* __restrict__ Y16)
{
    int row = blockIdx.x;
    int tid = threadIdx.x;
    const float4* y4 = (const float4*)(Y + (size_t)row * D_INNER);
    const float4* z4 = (const float4*)(ZX + (size_t)row * D_IN_PROJ + OFF_Z);
    const float4* w4 = (const float4*)norm_w;

    float4 gv[4];
    float sq = 0.f;
    #pragma unroll
    for (int i = 0; i < 4; i++) {
        int e = tid + 256 * i;
        float4 yv = y4[e];
        float4 zv = z4[e];
        float4 gg;
        gg.x = yv.x * silu_f(zv.x);
        gg.y = yv.y * silu_f(zv.y);
        gg.z = yv.z * silu_f(zv.z);
        gg.w = yv.w * silu_f(zv.w);
        sq += gg.x*gg.x + gg.y*gg.y + gg.z*gg.z + gg.w*gg.w;
        gv[i] = gg;
    }

    #pragma unroll
    for (int off = 16; off > 0; off >>= 1)
        sq += __shfl_xor_sync(0xffffffffu, sq, off);
    __shared__ float sred[8];
    int wid = tid >> 5, lane = tid & 31;
    if (lane == 0) sred[wid] = sq;
    __syncthreads();
    float tot = 0.f;
    #pragma unroll
    for (int i = 0; i < 8; i++) tot += sred[i];
    float scale = rsqrtf(tot * (1.0f / D_INNER) + EPSV);

    __half2* o2 = (__half2*)(Y16 + (size_t)row * D_INNER);
    #pragma unroll
    for (int i = 0; i < 4; i++) {
        int e = tid + 256 * i;
        float4 wv = w4[e];
        float4 gg = gv[i];
        gg.x *= scale * wv.x;
        gg.y *= scale * wv.y;
        gg.z *= scale * wv.z;
        gg.w *= scale * wv.w;
        o2[e * 2]     = __floats2half2_rn(gg.x, gg.y);
        o2[e * 2 + 1] = __floats2half2_rn(gg.z, gg.w);
    }
}

// ---------------------------------------------------------------------------
// Launch
// ---------------------------------------------------------------------------
extern "C" void kernel_launch(void* const* d_in, const int* in_sizes, int n_in,
                              void* d_out, int out_size)
{
    const float* hidden    = (const float*)d_in[0];
    const float* ln_w      = (const float*)d_in[1];
    const float* ln_b      = (const float*)d_in[2];
    const float* in_proj_w = (const float*)d_in[3];
    const float* dt_bias   = (const float*)d_in[4];
    const float* A_log     = (const float*)d_in[5];
    const float* Dp        = (const float*)d_in[6];
    const float* norm_w    = (const float*)d_in[7];
    const float* out_proj_w= (const float*)d_in[8];
    const float* fc1_w     = (const float*)d_in[9];
    const float* fc1_b     = (const float*)d_in[10];
    const float* fc2_w     = (const float*)d_in[11];
    const float* fc2_b     = (const float*)d_in[12];
    float* out = (float*)d_out;

    float* scratch = nullptr;
    cudaGetSymbolAddress((void**)&scratch, g_scratch);
    float*  ZX   = scratch + ZX_OFF;
    float*  Yf   = scratch + YF_OFF;
    float*  TMP  = scratch + TMP_OFF;
    __half* F16  = (__half*)(scratch + F16_OFF);
    __half* Wip  = F16 + WIP_OFF;
    __half* Wop  = F16 + WOP_OFF;
    __half* W1   = F16 + W1_OFF;
    __half* W2   = F16 + W2_OFF;
    __half* H16  = F16 + H16_OFF;
    __half* Y16  = F16 + Y16_OFF;
    __half* MLP1 = (__half*)(scratch + ZX_OFF);   // aliases ZX (dead by fc1)

    // 0. weight conversions (fp32 -> fp16)
    cvt_f16_kernel<<<(unsigned)(WIP_H / 8 / 256), 256>>>(in_proj_w,  Wip, WIP_H);
    cvt_f16_kernel<<<(unsigned)(WOP_H / 8 / 256), 256>>>(out_proj_w, Wop, WOP_H);
    cvt_f16_kernel<<<(unsigned)(W1_H  / 8 / 256), 256>>>(fc1_w,      W1,  W1_H);
    cvt_f16_kernel<<<(unsigned)(W2_H  / 8 / 256), 256>>>(fc2_w,      W2,  W2_H);

    // 1. LayerNorm -> fp16 H
    ln_kernel<<<TOKENS, 256>>>(hidden, ln_w, ln_b, H16);

    // 2. in_proj: ZX = H @ Wip^T  (4096 x 10304 x 2048), N-tail predicated
    hgemm_nt<0><<<dim3((D_IN_PROJ + 127) / 128, TOKENS / 128), 256>>>(
        H16, Wip, ZX, D_IN_PROJ, D_MODEL, nullptr, nullptr, nullptr);

    // 3. SSD scan -> Yf (fp32, pre-gate)
    scan_kernel<<<BATCH * NHEADS, 256>>>(ZX, dt_bias, A_log, Dp, Yf);

    // 4. gate + RMSNorm -> fp16 Y
    gate_norm_kernel<<<TOKENS, 256>>>(Yf, ZX, norm_w, Y16);

    // 5. out_proj: TMP = Y @ Wop^T  (4096 x 2048 x 4096)
    hgemm_nt<0><<<dim3(D_MODEL / 128, TOKENS / 128), 256>>>(
        Y16, Wop, TMP, D_MODEL, D_INNER, nullptr, nullptr, nullptr);

    // 6. fc1 + gelu -> fp16 MLP1  (4096 x 8192 x 2048)
    hgemm_nt<1><<<dim3(INTER / 128, TOKENS / 128), 256>>>(
        H16, W1, MLP1, INTER, D_MODEL, fc1_b, nullptr, nullptr);

    // 7. fc2 + bias + TMP + residual -> out  (4096 x 2048 x 8192)
    hgemm_nt<2><<<dim3(D_MODEL / 128, TOKENS / 128), 256>>>(
        MLP1, W2, out, D_MODEL, INTER, fc2_b, TMP, hidden);
}